// round 1
// baseline (speedup 1.0000x reference)
#include <cuda_runtime.h>

#define VOCAB 64
#define HID 64
#define SD 32
#define FD 16
#define SLD 16
#define BB 256
#define LL 2048

typedef unsigned long long u64;

// ---------- packed f32x2 helpers (ptxas only emits FFMA2 via PTX) ----------
__device__ __forceinline__ u64 ffma2(u64 a, u64 b, u64 c) {
    u64 d;
    asm("fma.rn.f32x2 %0, %1, %2, %3;" : "=l"(d) : "l"(a), "l"(b), "l"(c));
    return d;
}
__device__ __forceinline__ u64 fmul2(u64 a, u64 b) {
    u64 d;
    asm("mul.rn.f32x2 %0, %1, %2;" : "=l"(d) : "l"(a), "l"(b));
    return d;
}
__device__ __forceinline__ u64 fadd2(u64 a, u64 b) {
    u64 d;
    asm("add.rn.f32x2 %0, %1, %2;" : "=l"(d) : "l"(a), "l"(b));
    return d;
}
__device__ __forceinline__ float2 unpk(u64 u) {
    float2 f;
    asm("mov.b64 {%0,%1}, %2;" : "=f"(f.x), "=f"(f.y) : "l"(u));
    return f;
}
__device__ __forceinline__ u64 pk(float x, float y) {
    u64 u;
    asm("mov.b64 %0, {%1,%2};" : "=l"(u) : "f"(x), "f"(y));
    return u;
}

// ---------- token tables (device scratch; no allocation allowed) ----------
__device__ float g_tab_s[64 * SD];
__device__ float g_tab_f[64 * FD];
__device__ float g_tab_sl[64 * SLD];
__device__ float g_inv_s[64];
__device__ float g_inv_f[64];
__device__ float g_inv_sl[64];

// ============================================================================
// Stage 1: encoder + projections collapse to per-token tables (64 tokens).
// One block per token, 64 threads (one per hidden dim).
// ============================================================================
__global__ void tables_kernel(
    const float* __restrict__ embed,
    const float* __restrict__ w1, const float* __restrict__ b1,
    const float* __restrict__ w2, const float* __restrict__ b2,
    const float* __restrict__ ln_g, const float* __restrict__ ln_b,
    const float* __restrict__ sem_w, const float* __restrict__ sem_b,
    const float* __restrict__ fast_w, const float* __restrict__ fast_b,
    const float* __restrict__ slow_w, const float* __restrict__ slow_b)
{
    int tok = blockIdx.x;
    int tid = threadIdx.x;  // 0..63
    __shared__ float se[HID], sh1[2 * HID], sx[HID], sh[HID], sk[64];

    se[tid] = embed[tok * HID + tid];
    __syncthreads();

    // hidden = relu(e @ w1 + b1), w1 is [HID, 2H] row-major
    #pragma unroll
    for (int rep = 0; rep < 2; rep++) {
        int m = tid + rep * 64;
        float a = b1[m];
        #pragma unroll 8
        for (int j = 0; j < HID; j++) a = fmaf(se[j], w1[j * (2 * HID) + m], a);
        sh1[m] = fmaxf(a, 0.0f);
    }
    __syncthreads();

    // ff = hidden @ w2 + b2 ; x = e + ff
    float ff = b2[tid];
    #pragma unroll 8
    for (int m = 0; m < 2 * HID; m++) ff = fmaf(sh1[m], w2[m * HID + tid], ff);
    float x = se[tid] + ff;
    sx[tid] = x;
    __syncthreads();

    // layernorm
    float mu = 0.0f;
    #pragma unroll 8
    for (int j = 0; j < HID; j++) mu += sx[j];
    mu *= (1.0f / HID);
    float var = 0.0f;
    #pragma unroll 8
    for (int j = 0; j < HID; j++) { float d = sx[j] - mu; var = fmaf(d, d, var); }
    var *= (1.0f / HID);
    float hv = (x - mu) * rsqrtf(var + 1e-5f) * ln_g[tid] + ln_b[tid];
    sh[tid] = hv;
    __syncthreads();

    // projections: tid 0-31 -> sem, 32-47 -> fast, 48-63 -> slow
    float key;
    if (tid < 32) {
        int d = tid;
        float a = sem_b[d];
        #pragma unroll 8
        for (int j = 0; j < HID; j++) a = fmaf(sh[j], sem_w[j * SD + d], a);
        g_tab_s[tok * SD + d] = a; key = a;
    } else if (tid < 48) {
        int d = tid - 32;
        float a = fast_b[d];
        #pragma unroll 8
        for (int j = 0; j < HID; j++) a = fmaf(sh[j], fast_w[j * FD + d], a);
        g_tab_f[tok * FD + d] = a; key = a;
    } else {
        int d = tid - 48;
        float a = slow_b[d];
        #pragma unroll 8
        for (int j = 0; j < HID; j++) a = fmaf(sh[j], slow_w[j * SLD + d], a);
        g_tab_sl[tok * SLD + d] = a; key = a;
    }
    sk[tid] = key;
    __syncthreads();

    if (tid == 0) {
        float s = 0.0f;
        for (int j = 0; j < 32; j++) s = fmaf(sk[j], sk[j], s);
        g_inv_s[tok] = 1.0f / (s + 1e-6f);
    } else if (tid == 1) {
        float s = 0.0f;
        for (int j = 32; j < 48; j++) s = fmaf(sk[j], sk[j], s);
        g_inv_f[tok] = 1.0f / (s + 1e-6f);
    } else if (tid == 2) {
        float s = 0.0f;
        for (int j = 48; j < 64; j++) s = fmaf(sk[j], sk[j], s);
        g_inv_sl[tok] = 1.0f / (s + 1e-6f);
    }
}

// ---------- scan helpers ----------
__device__ __forceinline__ void ld16(u64* k, const float* p) {
    const ulonglong2* q = (const ulonglong2*)p;
    ulonglong2 q0 = q[0], q1 = q[1], q2 = q[2], q3 = q[3];
    k[0] = q0.x; k[1] = q0.y; k[2] = q1.x; k[3] = q1.y;
    k[4] = q2.x; k[5] = q2.y; k[6] = q3.x; k[7] = q3.y;
}

__device__ __forceinline__ float dot8(const u64* M, const u64* k) {
    u64 a0 = fmul2(M[0], k[0]);
    u64 a1 = fmul2(M[1], k[1]);
    u64 a2 = fmul2(M[2], k[2]);
    u64 a3 = fmul2(M[3], k[3]);
    a0 = ffma2(M[4], k[4], a0);
    a1 = ffma2(M[5], k[5], a1);
    a2 = ffma2(M[6], k[6], a2);
    a3 = ffma2(M[7], k[7], a3);
    a0 = fadd2(fadd2(a0, a1), fadd2(a2, a3));
    float2 f = unpk(a0);
    return f.x + f.y;
}

// ============================================================================
// Stage 2: the sequential delta-rule scan + fused readout.
// One block per batch, 3 warps:
//   warp 0: Ms rows 0-15  (lane = row + 16*half, half-row of 16 floats)
//   warp 1: Ms rows 16-31 (same half-row layout)
//   warp 2: lanes 0-15 own Mef rows, lanes 16-31 own Mes rows (full rows)
// Rows of M evolve independently, so no communication except one shfl_xor(16)
// to combine dot-product halves in warps 0/1.
// ============================================================================
__global__ void __launch_bounds__(96, 1) scan_kernel(
    const int* __restrict__ seq,
    const float* __restrict__ out_w, const float* __restrict__ out_b,
    float* __restrict__ out)
{
    __shared__ __align__(16) float s_tab_s[64 * SD];
    __shared__ __align__(16) float s_tab_f[64 * FD];
    __shared__ __align__(16) float s_tab_sl[64 * SLD];
    __shared__ float s_inv_s[64], s_inv_f[64], s_inv_sl[64];
    __shared__ int s_seq[LL];
    __shared__ float s_c[64];

    int b = blockIdx.x;
    int tid = threadIdx.x;

    for (int i = tid; i < 64 * SD; i += 96) s_tab_s[i] = g_tab_s[i];
    for (int i = tid; i < 64 * FD; i += 96) s_tab_f[i] = g_tab_f[i];
    for (int i = tid; i < 64 * SLD; i += 96) s_tab_sl[i] = g_tab_sl[i];
    if (tid < 64) {
        s_inv_s[tid] = g_inv_s[tid];
        s_inv_f[tid] = g_inv_f[tid];
        s_inv_sl[tid] = g_inv_sl[tid];
    }
    const int* sq = seq + (size_t)b * LL;
    for (int i = tid; i < LL; i += 96) s_seq[i] = sq[i];
    __syncthreads();

    int wid = tid >> 5;
    int lane = tid & 31;

    if (wid < 2) {
        // ---- semantic memory Ms (32x32), w = 1 ----
        int r = (lane & 15) | (wid << 4);  // global row 0..31
        int h = lane >> 4;                  // which 16-col half this lane owns
        const float* base = s_tab_s + 16 * h;

        u64 M[8];
        #pragma unroll
        for (int j = 0; j < 8; j++) M[j] = 0ull;

        int tok = s_seq[0];
        u64 k[8]; float ki, minv;
        ld16(k, base + tok * SD);
        ki = s_tab_s[tok * SD + r];
        minv = -s_inv_s[tok];

        for (int t = 0; t < LL - 1; t++) {
            // prefetch next key (t = LL-2 prefetches the readout key)
            int tokn = s_seq[t + 1];
            u64 kn[8];
            ld16(kn, base + tokn * SD);
            float kin = s_tab_s[tokn * SD + r];
            float minvn = -s_inv_s[tokn];

            float part = dot8(M, k);
            float vp = part + __shfl_xor_sync(0xffffffffu, part, 16);
            float dv = fmaf(vp, minv, ki);  // k_i - (M k)_i / (||k||^2 + eps)
            u64 c2 = pk(dv, dv);            // w = 1
            #pragma unroll
            for (int j = 0; j < 8; j++) M[j] = ffma2(c2, k[j], M[j]);

            #pragma unroll
            for (int j = 0; j < 8; j++) k[j] = kn[j];
            ki = kin; minv = minvn;
        }
        // readout: cs = Ms @ k_last (k currently holds key at position L-1)
        float part = dot8(M, k);
        float vp = part + __shfl_xor_sync(0xffffffffu, part, 16);
        if (h == 0) s_c[r] = vp;
    } else {
        // ---- fast (lanes 0-15) / slow (lanes 16-31) episodic memories 16x16 ----
        int sl = lane >> 4;
        int r = lane & 15;
        const float* tab = sl ? s_tab_sl : s_tab_f;
        const float* invt = sl ? s_inv_sl : s_inv_f;

        u64 M[8];
        #pragma unroll
        for (int j = 0; j < 8; j++) M[j] = 0ull;

        int tok = s_seq[0];
        u64 k[8]; float ki, minv;
        ld16(k, tab + tok * 16);
        ki = tab[tok * 16 + r];
        minv = -invt[tok];

        const float invL = 1.0f / (float)LL;
        for (int t = 0; t < LL - 1; t++) {
            int tokn = s_seq[t + 1];
            u64 kn[8];
            ld16(kn, tab + tokn * 16);
            float kin = tab[tokn * 16 + r];
            float minvn = -invt[tokn];

            float wf = (float)(t + 1) * invL;
            float w = sl ? sqrtf(wf) : wf;

            float vp = dot8(M, k);  // full row, no reduce needed
            float dv = fmaf(vp, minv, ki);
            float c = w * dv;
            u64 c2 = pk(c, c);
            #pragma unroll
            for (int j = 0; j < 8; j++) M[j] = ffma2(c2, k[j], M[j]);

            #pragma unroll
            for (int j = 0; j < 8; j++) k[j] = kn[j];
            ki = kin; minv = minvn;
        }
        float vp = dot8(M, k);
        s_c[32 + (sl << 4) + r] = vp;
    }
    __syncthreads();

    // fused readout: out = concat(cs, cef, ces) @ out_w + out_b
    if (tid < 64) {
        float acc = out_b[tid];
        #pragma unroll 8
        for (int d = 0; d < 64; d++) acc = fmaf(s_c[d], out_w[d * VOCAB + tid], acc);
        out[b * VOCAB + tid] = acc;
    }
}

extern "C" void kernel_launch(void* const* d_in, const int* in_sizes, int n_in,
                              void* d_out, int out_size) {
    const int*   seq    = (const int*)  d_in[0];
    const float* embed  = (const float*)d_in[1];
    const float* w1     = (const float*)d_in[2];
    const float* b1     = (const float*)d_in[3];
    const float* w2     = (const float*)d_in[4];
    const float* b2     = (const float*)d_in[5];
    const float* ln_g   = (const float*)d_in[6];
    const float* ln_b   = (const float*)d_in[7];
    const float* sem_w  = (const float*)d_in[8];
    const float* sem_b  = (const float*)d_in[9];
    const float* fast_w = (const float*)d_in[10];
    const float* fast_b = (const float*)d_in[11];
    const float* slow_w = (const float*)d_in[12];
    const float* slow_b = (const float*)d_in[13];
    const float* out_w  = (const float*)d_in[14];
    const float* out_b  = (const float*)d_in[15];
    float* out = (float*)d_out;

    tables_kernel<<<64, 64>>>(embed, w1, b1, w2, b2, ln_g, ln_b,
                              sem_w, sem_b, fast_w, fast_b, slow_w, slow_b);
    scan_kernel<<<BB, 96>>>(seq, out_w, out_b, out);
}

// round 3
// speedup vs baseline: 1.9797x; 1.9797x over previous
#include <cuda_runtime.h>

#define VOCAB 64
#define HID 64
#define SD 32
#define FD 16
#define SLD 16
#define BB 256
#define LL 2048

typedef unsigned long long u64;

// ---------- packed f32x2 helpers ----------
__device__ __forceinline__ u64 ffma2(u64 a, u64 b, u64 c) {
    u64 d;
    asm("fma.rn.f32x2 %0, %1, %2, %3;" : "=l"(d) : "l"(a), "l"(b), "l"(c));
    return d;
}
__device__ __forceinline__ u64 fmul2(u64 a, u64 b) {
    u64 d;
    asm("mul.rn.f32x2 %0, %1, %2;" : "=l"(d) : "l"(a), "l"(b));
    return d;
}
__device__ __forceinline__ float2 unpk(u64 u) {
    float2 f;
    asm("mov.b64 {%0,%1}, %2;" : "=f"(f.x), "=f"(f.y) : "l"(u));
    return f;
}
__device__ __forceinline__ u64 pk(float x, float y) {
    u64 u;
    asm("mov.b64 %0, {%1,%2};" : "=l"(u) : "f"(x), "f"(y));
    return u;
}
__device__ __forceinline__ float sqrt_approx(float x) {
    float r;
    asm("sqrt.approx.f32 %0, %1;" : "=f"(r) : "f"(x));
    return r;
}

// ---------- global scratch (no allocation allowed) ----------
__device__ float g_tab_s[64 * SD];
__device__ float g_tab_f[64 * FD];
__device__ float g_tab_sl[64 * SLD];
__device__ float g_inv3[64 * 4];     // [tok][group]
__device__ float g_gram0[64 * 64];   // sem  Gram
__device__ float g_gram1[64 * 64];   // fast Gram
__device__ float g_gram2[64 * 64];   // slow Gram

// ============================================================================
// Stage 1: encoder collapses to 64-token key tables.
// ============================================================================
__global__ void tables_kernel(
    const float* __restrict__ embed,
    const float* __restrict__ w1, const float* __restrict__ b1,
    const float* __restrict__ w2, const float* __restrict__ b2,
    const float* __restrict__ ln_g, const float* __restrict__ ln_b,
    const float* __restrict__ sem_w, const float* __restrict__ sem_b,
    const float* __restrict__ fast_w, const float* __restrict__ fast_b,
    const float* __restrict__ slow_w, const float* __restrict__ slow_b)
{
    int tok = blockIdx.x;
    int tid = threadIdx.x;  // 0..63
    __shared__ float se[HID], sh1[2 * HID], sx[HID], sh[HID], sk[64];

    se[tid] = embed[tok * HID + tid];
    __syncthreads();

    #pragma unroll
    for (int rep = 0; rep < 2; rep++) {
        int m = tid + rep * 64;
        float a = b1[m];
        #pragma unroll 8
        for (int j = 0; j < HID; j++) a = fmaf(se[j], w1[j * (2 * HID) + m], a);
        sh1[m] = fmaxf(a, 0.0f);
    }
    __syncthreads();

    float ff = b2[tid];
    #pragma unroll 8
    for (int m = 0; m < 2 * HID; m++) ff = fmaf(sh1[m], w2[m * HID + tid], ff);
    float x = se[tid] + ff;
    sx[tid] = x;
    __syncthreads();

    float mu = 0.0f;
    #pragma unroll 8
    for (int j = 0; j < HID; j++) mu += sx[j];
    mu *= (1.0f / HID);
    float var = 0.0f;
    #pragma unroll 8
    for (int j = 0; j < HID; j++) { float d = sx[j] - mu; var = fmaf(d, d, var); }
    var *= (1.0f / HID);
    float hv = (x - mu) * rsqrtf(var + 1e-5f) * ln_g[tid] + ln_b[tid];
    sh[tid] = hv;
    __syncthreads();

    float key;
    if (tid < 32) {
        int d = tid;
        float a = sem_b[d];
        #pragma unroll 8
        for (int j = 0; j < HID; j++) a = fmaf(sh[j], sem_w[j * SD + d], a);
        g_tab_s[tok * SD + d] = a; key = a;
    } else if (tid < 48) {
        int d = tid - 32;
        float a = fast_b[d];
        #pragma unroll 8
        for (int j = 0; j < HID; j++) a = fmaf(sh[j], fast_w[j * FD + d], a);
        g_tab_f[tok * FD + d] = a; key = a;
    } else {
        int d = tid - 48;
        float a = slow_b[d];
        #pragma unroll 8
        for (int j = 0; j < HID; j++) a = fmaf(sh[j], slow_w[j * SLD + d], a);
        g_tab_sl[tok * SLD + d] = a; key = a;
    }
    sk[tid] = key;
    __syncthreads();

    if (tid == 0) {
        float s = 0.0f;
        for (int j = 0; j < 32; j++) s = fmaf(sk[j], sk[j], s);
        g_inv3[tok * 4 + 0] = 1.0f / (s + 1e-6f);
    } else if (tid == 1) {
        float s = 0.0f;
        for (int j = 32; j < 48; j++) s = fmaf(sk[j], sk[j], s);
        g_inv3[tok * 4 + 1] = 1.0f / (s + 1e-6f);
    } else if (tid == 2) {
        float s = 0.0f;
        for (int j = 48; j < 64; j++) s = fmaf(sk[j], sk[j], s);
        g_inv3[tok * 4 + 2] = 1.0f / (s + 1e-6f);
    }
}

// ============================================================================
// Stage 2: per-memory token Gram matrices G[a][b] = k_a . k_b
// ============================================================================
__global__ void gram_kernel()
{
    int a = blockIdx.x;
    int tid = threadIdx.x;  // 0..63
    __shared__ float rs[32], rf[16], rsl[16];
    if (tid < 32) rs[tid] = g_tab_s[a * SD + tid];
    else if (tid < 48) rf[tid - 32] = g_tab_f[a * FD + (tid - 32)];
    else rsl[tid - 48] = g_tab_sl[a * SLD + (tid - 48)];
    __syncthreads();

    int b = tid;
    float ds = 0.0f, df = 0.0f, dsl = 0.0f;
    #pragma unroll 8
    for (int j = 0; j < 32; j++) ds = fmaf(rs[j], g_tab_s[b * SD + j], ds);
    #pragma unroll 8
    for (int j = 0; j < 16; j++) df = fmaf(rf[j], g_tab_f[b * FD + j], df);
    #pragma unroll 8
    for (int j = 0; j < 16; j++) dsl = fmaf(rsl[j], g_tab_sl[b * SLD + j], dsl);
    g_gram0[a * 64 + b] = ds;
    g_gram1[a * 64 + b] = df;
    g_gram2[a * 64 + b] = dsl;
}

// ============================================================================
// Stage 3: backward vector scan with scatter-at-produce gram pipelining.
//   c  = sum_s w_s (k_s . q^{(s+1)}) k_s
//   q^{(s)} = q^{(s+1)} - w_s*alpha_s*(k_s . q^{(s+1)}) k_s
// Dot products are computed 4 steps ahead against a stale q; each computed
// a_s is immediately scattered into the 3 pending dot values via the token
// Gram matrix, so every entry is fully corrected when consumed (exact).
// One warp = one batch. Lanes: 0-15 sem (2 floats), 16-23 fast, 24-31 slow.
// 128 blocks x 64 threads (2 batches/block), 1 block/SM.
// ============================================================================

// shared layout (bytes)
#define SM_TAB_S   0
#define SM_TAB_F   8192
#define SM_TAB_SL  12288
#define SM_GRAM0   16384
#define SM_GRAM1   32784   /* +16400: 16B pad shifts banks */
#define SM_GRAM2   49184
#define SM_INV3    65584
#define SM_SC      66608
#define SM_SEQ     67136
#define SM_TOTAL   (67136 + 2 * 2048 * 4)

__global__ void __launch_bounds__(64, 1) scan_kernel(
    const int* __restrict__ seq,
    const float* __restrict__ out_w, const float* __restrict__ out_b,
    float* __restrict__ out)
{
    extern __shared__ __align__(16) unsigned char smem[];
    float* smf = (float*)smem;
    int tid = threadIdx.x;

    // ---- fill shared: tables, grams, inv, seqs (vectorized) ----
    {
        float4* d;
        const float4* s;
        d = (float4*)(smem + SM_TAB_S);  s = (const float4*)g_tab_s;
        for (int i = tid; i < 512; i += 64) d[i] = s[i];
        d = (float4*)(smem + SM_TAB_F);  s = (const float4*)g_tab_f;
        for (int i = tid; i < 256; i += 64) d[i] = s[i];
        d = (float4*)(smem + SM_TAB_SL); s = (const float4*)g_tab_sl;
        for (int i = tid; i < 256; i += 64) d[i] = s[i];
        d = (float4*)(smem + SM_GRAM0);  s = (const float4*)g_gram0;
        for (int i = tid; i < 1024; i += 64) d[i] = s[i];
        d = (float4*)(smem + SM_GRAM1);  s = (const float4*)g_gram1;
        for (int i = tid; i < 1024; i += 64) d[i] = s[i];
        d = (float4*)(smem + SM_GRAM2);  s = (const float4*)g_gram2;
        for (int i = tid; i < 1024; i += 64) d[i] = s[i];
        d = (float4*)(smem + SM_INV3);   s = (const float4*)g_inv3;
        for (int i = tid; i < 64; i += 64) d[i] = s[i];
        int4* di = (int4*)(smem + SM_SEQ);
        const int4* si = (const int4*)(seq + (size_t)blockIdx.x * 2 * LL);
        for (int i = tid; i < 1024; i += 64) di[i] = si[i];
    }
    __syncthreads();

    int warp = tid >> 5;
    int lane = tid & 31;
    int batch = blockIdx.x * 2 + warp;

    // lane group: 0 = sem (16 lanes), 1 = fast (8), 2 = slow (8)
    int g = lane < 16 ? 0 : (lane < 24 ? 1 : 2);
    int e = lane - (g == 0 ? 0 : (g == 1 ? 16 : 24));
    const float* tabb = smf + (g == 0 ? 0 : (g == 1 ? 2048 : 3072)) + e * 2;
    int kstr = (g == 0 ? 32 : 16);
    const float* gb = (const float*)(smem + (g == 0 ? SM_GRAM0 : (g == 1 ? SM_GRAM1 : SM_GRAM2)));
    const float* invb = (const float*)(smem + SM_INV3) + g;
    const int* sq = (const int*)(smem + SM_SEQ) + warp * LL;
    float* scp = (float*)(smem + SM_SC) + warp * 64;
    bool is_sem = (g == 0);

    // ---- init: q = k_{L-1}, c = 0 ----
    int tau_last = sq[LL - 1];
    u64 q = *(const u64*)(tabb + tau_last * kstr);
    u64 c = pk(0.0f, 0.0f);

    // ---- pipeline rings, depth 4 (all produce-written) ----
    float R_r[4], inv_r[4];
    int tok_r[4];
    u64 k_r[4];

    #pragma unroll
    for (int j = 0; j < 4; j++) {
        int sp = 2046 - j;               // consumed at iter j
        int tau = sq[sp];
        tok_r[j] = tau;
        inv_r[j] = invb[tau * 4];
        u64 kj = *(const u64*)(tabb + tau * kstr);
        k_r[j] = kj;
        u64 pm = fmul2(kj, q);
        float2 pf = unpk(pm);
        float p = pf.x + pf.y;
        p += __shfl_xor_sync(0xffffffffu, p, 1);
        p += __shfl_xor_sync(0xffffffffu, p, 2);
        p += __shfl_xor_sync(0xffffffffu, p, 4);
        float p8 = p + __shfl_xor_sync(0xffffffffu, p, 8);
        R_r[j] = is_sem ? p8 : p;
    }
    // Entry j (s = 2046-j) was computed against q^{(2047)}; it will receive
    // its j missing corrections from a_{2046..2046-j+1} scattered by iters < j.

    // ---- main loop: s = 2046 - it, it in [0, 2048) (last iter s = -1, w = 0) ----
    const float invL = 1.0f / (float)LL;
    float uf = 2047.0f;   // u = s + 1

    #pragma unroll 4
    for (int it = 0; it < 2048; ++it) {
        int slot = it & 3;
        int ts = tok_r[slot];
        const float* grow = gb + ts * 64;
        // G loads for the scatter — addresses known now, values needed after a.
        float G1 = grow[tok_r[(slot + 1) & 3]];
        float G2 = grow[tok_r[(slot + 2) & 3]];
        float G3 = grow[tok_r[(slot + 3) & 3]];

        float d = R_r[slot];   // fully corrected

        // step weight per group (uf == 0 on the final dummy iter -> all zero)
        float wf = uf * invL;
        float wsl = sqrt_approx(wf);
        float wsem = (uf > 0.5f) ? 1.0f : 0.0f;
        float w = is_sem ? wsem : (g == 1 ? wf : wsl);

        float wd = w * d;
        float a = wd * inv_r[slot];
        u64 kc = k_r[slot];
        c = ffma2(pk(wd, wd), kc, c);
        q = ffma2(pk(-a, -a), kc, q);

        // scatter correction -a_s * G(tok_pending, tok_s) into pending entries
        float na = -a;
        R_r[(slot + 1) & 3] = fmaf(na, G1, R_r[(slot + 1) & 3]);
        R_r[(slot + 2) & 3] = fmaf(na, G2, R_r[(slot + 2) & 3]);
        R_r[(slot + 3) & 3] = fmaf(na, G3, R_r[(slot + 3) & 3]);

        // produce: dot for step s-4 against the freshly updated q^{(s)}
        int sn = 2046 - it - 4;
        int idx = sn < 0 ? 0 : sn;
        int tau = sq[idx];
        tok_r[slot] = tau;
        inv_r[slot] = invb[tau * 4];
        u64 kn = *(const u64*)(tabb + tau * kstr);
        k_r[slot] = kn;

        u64 pm = fmul2(kn, q);
        float2 pf = unpk(pm);
        float p = pf.x + pf.y;
        p += __shfl_xor_sync(0xffffffffu, p, 1);
        p += __shfl_xor_sync(0xffffffffu, p, 2);
        p += __shfl_xor_sync(0xffffffffu, p, 4);
        float p8 = p + __shfl_xor_sync(0xffffffffu, p, 8);
        R_r[slot] = is_sem ? p8 : p;

        uf -= 1.0f;
    }

    // ---- write c slices: [sem 0..31][fast 32..47][slow 48..63] ----
    {
        int off = (g == 0) ? 2 * e : (g == 1 ? 32 + 2 * e : 48 + 2 * e);
        float2 cf = unpk(c);
        *(float2*)(scp + off) = cf;
    }
    __syncwarp();

    // ---- fused readout: out[batch] = c_all @ out_w + out_b, 2 cols/lane ----
    {
        int v0 = 2 * lane;
        const float2* W = (const float2*)out_w;
        float2 bb = *(const float2*)(out_b + v0);
        float acc0 = bb.x, acc1 = bb.y;
        #pragma unroll 8
        for (int d = 0; d < 64; d++) {
            float cd = scp[d];
            float2 wv = W[d * 32 + lane];
            acc0 = fmaf(cd, wv.x, acc0);
            acc1 = fmaf(cd, wv.y, acc1);
        }
        *(float2*)(out + batch * VOCAB + v0) = make_float2(acc0, acc1);
    }
}

extern "C" void kernel_launch(void* const* d_in, const int* in_sizes, int n_in,
                              void* d_out, int out_size) {
    const int*   seq    = (const int*)  d_in[0];
    const float* embed  = (const float*)d_in[1];
    const float* w1     = (const float*)d_in[2];
    const float* b1     = (const float*)d_in[3];
    const float* w2     = (const float*)d_in[4];
    const float* b2     = (const float*)d_in[5];
    const float* ln_g   = (const float*)d_in[6];
    const float* ln_b   = (const float*)d_in[7];
    const float* sem_w  = (const float*)d_in[8];
    const float* sem_b  = (const float*)d_in[9];
    const float* fast_w = (const float*)d_in[10];
    const float* fast_b = (const float*)d_in[11];
    const float* slow_w = (const float*)d_in[12];
    const float* slow_b = (const float*)d_in[13];
    const float* out_w  = (const float*)d_in[14];
    const float* out_b  = (const float*)d_in[15];
    float* out = (float*)d_out;

    cudaFuncSetAttribute(scan_kernel,
                         cudaFuncAttributeMaxDynamicSharedMemorySize, SM_TOTAL);

    tables_kernel<<<64, 64>>>(embed, w1, b1, w2, b2, ln_g, ln_b,
                              sem_w, sem_b, fast_w, fast_b, slow_w, slow_b);
    gram_kernel<<<64, 64>>>();
    scan_kernel<<<BB / 2, 64, SM_TOTAL>>>(seq, out_w, out_b, out);
}

// round 16
// speedup vs baseline: 2.0444x; 1.0327x over previous
#include <cuda_runtime.h>

#define VOCAB 64
#define HID 64
#define SD 32
#define FD 16
#define SLD 16
#define BB 256
#define LL 2048

typedef unsigned long long u64;

// ---------- packed f32x2 helpers ----------
__device__ __forceinline__ u64 ffma2(u64 a, u64 b, u64 c) {
    u64 d;
    asm("fma.rn.f32x2 %0, %1, %2, %3;" : "=l"(d) : "l"(a), "l"(b), "l"(c));
    return d;
}
__device__ __forceinline__ u64 fmul2(u64 a, u64 b) {
    u64 d;
    asm("mul.rn.f32x2 %0, %1, %2;" : "=l"(d) : "l"(a), "l"(b));
    return d;
}
__device__ __forceinline__ float2 unpk(u64 u) {
    float2 f;
    asm("mov.b64 {%0,%1}, %2;" : "=f"(f.x), "=f"(f.y) : "l"(u));
    return f;
}
__device__ __forceinline__ u64 pk(float x, float y) {
    u64 u;
    asm("mov.b64 %0, {%1,%2};" : "=l"(u) : "f"(x), "f"(y));
    return u;
}
__device__ __forceinline__ float sqrt_approx(float x) {
    float r;
    asm("sqrt.approx.f32 %0, %1;" : "=f"(r) : "f"(x));
    return r;
}

// ---------- global scratch ----------
__device__ float g_tab_s[64 * SD];
__device__ float g_tab_f[64 * FD];
__device__ float g_tab_sl[64 * SLD];
__device__ float g_tabi_s[64 * SD];    // inv-scaled keys
__device__ float g_tabi_f[64 * FD];
__device__ float g_tabi_sl[64 * SLD];
__device__ float g_inv3[64 * 4];
__device__ float g_gram0[64 * 64];     // ROW-scaled: G'(a,b) = (k_a.k_b)*inv_a
__device__ float g_gram1[64 * 64];
__device__ float g_gram2[64 * 64];

// ============================================================================
// Stage 1: encoder -> 64-token key tables. 16 blocks x 256 threads,
// 4 tokens/block. All weights staged to smem first (high-MLP fill).
// ============================================================================
// smem float offsets
#define TK_W1    0
#define TK_W2    8192
#define TK_PW    16384
#define TK_B1    20480
#define TK_B2    20608
#define TK_LNG   20672
#define TK_LNB   20736
#define TK_PB    20800
#define TK_E     20864
#define TK_H1    21120
#define TK_X     21632
#define TK_H     21888
#define TK_K     22144
#define TK_TOTF  22400

__global__ void __launch_bounds__(256, 1) tables_kernel(
    const float* __restrict__ embed,
    const float* __restrict__ w1, const float* __restrict__ b1,
    const float* __restrict__ w2, const float* __restrict__ b2,
    const float* __restrict__ ln_g, const float* __restrict__ ln_b,
    const float* __restrict__ sem_w, const float* __restrict__ sem_b,
    const float* __restrict__ fast_w, const float* __restrict__ fast_b,
    const float* __restrict__ slow_w, const float* __restrict__ slow_b)
{
    extern __shared__ float sm[];
    int tid = threadIdx.x;
    int tg = tid >> 6;      // token group 0..3
    int t = tid & 63;
    int tok = blockIdx.x * 4 + tg;

    // ---- stage weights (vectorized, high MLP) ----
    {
        float4* d; const float4* s;
        d = (float4*)(sm + TK_W1); s = (const float4*)w1;
        #pragma unroll
        for (int i = 0; i < 8; i++) d[tid + i * 256] = s[tid + i * 256];
        d = (float4*)(sm + TK_W2); s = (const float4*)w2;
        #pragma unroll
        for (int i = 0; i < 8; i++) d[tid + i * 256] = s[tid + i * 256];
        // packed projection weights: [j][0:32]=sem, [32:48]=fast, [48:64]=slow
        for (int i = tid; i < 64 * 32; i += 256) {
            int j = i >> 5, dd = i & 31;
            sm[TK_PW + j * 64 + dd] = sem_w[i];
        }
        for (int i = tid; i < 64 * 16; i += 256) {
            int j = i >> 4, dd = i & 15;
            sm[TK_PW + j * 64 + 32 + dd] = fast_w[i];
            sm[TK_PW + j * 64 + 48 + dd] = slow_w[i];
        }
        if (tid < 128) sm[TK_B1 + tid] = b1[tid];
        if (tid < 64) {
            sm[TK_B2 + tid] = b2[tid];
            sm[TK_LNG + tid] = ln_g[tid];
            sm[TK_LNB + tid] = ln_b[tid];
            sm[TK_PB + tid] = tid < 32 ? sem_b[tid]
                            : (tid < 48 ? fast_b[tid - 32] : slow_b[tid - 48]);
        }
        sm[TK_E + tg * 64 + t] = embed[tok * 64 + t];
    }
    __syncthreads();

    float* se  = sm + TK_E  + tg * 64;
    float* sh1 = sm + TK_H1 + tg * 128;
    float* sx  = sm + TK_X  + tg * 64;
    float* shv = sm + TK_H  + tg * 64;
    float* sk  = sm + TK_K  + tg * 64;

    // phase 1: hidden = relu(e @ w1 + b1)
    {
        float a0 = sm[TK_B1 + t], a1 = sm[TK_B1 + 64 + t];
        #pragma unroll 8
        for (int j = 0; j < 64; j++) {
            float ej = se[j];
            a0 = fmaf(ej, sm[TK_W1 + j * 128 + t], a0);
            a1 = fmaf(ej, sm[TK_W1 + j * 128 + t + 64], a1);
        }
        sh1[t] = fmaxf(a0, 0.0f);
        sh1[t + 64] = fmaxf(a1, 0.0f);
    }
    __syncthreads();

    // phase 2: x = e + hidden @ w2 + b2
    float x;
    {
        float ff = sm[TK_B2 + t];
        #pragma unroll 8
        for (int m = 0; m < 128; m++) ff = fmaf(sh1[m], sm[TK_W2 + m * 64 + t], ff);
        x = se[t] + ff;
        sx[t] = x;
    }
    __syncthreads();

    // layernorm
    {
        float mu = 0.0f;
        #pragma unroll 8
        for (int j = 0; j < 64; j++) mu += sx[j];
        mu *= (1.0f / HID);
        float var = 0.0f;
        #pragma unroll 8
        for (int j = 0; j < 64; j++) { float dd = sx[j] - mu; var = fmaf(dd, dd, var); }
        var *= (1.0f / HID);
        shv[t] = (x - mu) * rsqrtf(var + 1e-5f) * sm[TK_LNG + t] + sm[TK_LNB + t];
    }
    __syncthreads();

    // projections (uniform packed matvec)
    {
        float a = sm[TK_PB + t];
        #pragma unroll 8
        for (int j = 0; j < 64; j++) a = fmaf(shv[j], sm[TK_PW + j * 64 + t], a);
        if (t < 32) g_tab_s[tok * SD + t] = a;
        else if (t < 48) g_tab_f[tok * FD + (t - 32)] = a;
        else g_tab_sl[tok * SLD + (t - 48)] = a;
        sk[t] = a;
    }
    __syncthreads();

    if (t == 0) {
        float s = 0.0f;
        #pragma unroll
        for (int j = 0; j < 32; j++) s = fmaf(sk[j], sk[j], s);
        g_inv3[tok * 4 + 0] = 1.0f / (s + 1e-6f);
    } else if (t == 1) {
        float s = 0.0f;
        #pragma unroll
        for (int j = 32; j < 48; j++) s = fmaf(sk[j], sk[j], s);
        g_inv3[tok * 4 + 1] = 1.0f / (s + 1e-6f);
    } else if (t == 2) {
        float s = 0.0f;
        #pragma unroll
        for (int j = 48; j < 64; j++) s = fmaf(sk[j], sk[j], s);
        g_inv3[tok * 4 + 2] = 1.0f / (s + 1e-6f);
    }
}

// ============================================================================
// Stage 2: ROW-scaled Gram matrices G'(a,b) = (k_a.k_b)*inv_a, plus
// inv-scaled key tables. The scan reads grow = G'[tok_consumed * 64] and
// needs k_pending . (inv_consumed * k_consumed) = G(consumed,pending)*inv_consumed
// -> scale by the ROW index a. 16 blocks x 256 threads, tables in smem.
// ============================================================================
__global__ void __launch_bounds__(256, 1) gram_kernel()
{
    __shared__ float ts[2048], tf[1024], tsl[1024];
    int tid = threadIdx.x;
    for (int i = tid; i < 512; i += 256) ((float4*)ts)[i] = ((const float4*)g_tab_s)[i];
    if (tid < 256) {
        ((float4*)tf)[tid] = ((const float4*)g_tab_f)[tid];
        ((float4*)tsl)[tid] = ((const float4*)g_tab_sl)[tid];
    }
    __syncthreads();

    int a = blockIdx.x * 4 + (tid >> 6);
    int b = tid & 63;
    float ds = 0.0f, df = 0.0f, dsl = 0.0f;
    #pragma unroll 8
    for (int j = 0; j < 32; j++) ds = fmaf(ts[a * 32 + j], ts[b * 32 + j], ds);
    #pragma unroll 8
    for (int j = 0; j < 16; j++) df = fmaf(tf[a * 16 + j], tf[b * 16 + j], df);
    #pragma unroll 8
    for (int j = 0; j < 16; j++) dsl = fmaf(tsl[a * 16 + j], tsl[b * 16 + j], dsl);
    g_gram0[a * 64 + b] = ds * g_inv3[a * 4 + 0];    // ROW scale (inv of a)
    g_gram1[a * 64 + b] = df * g_inv3[a * 4 + 1];
    g_gram2[a * 64 + b] = dsl * g_inv3[a * 4 + 2];

    // inv-scaled key tables (this block's 4 tokens)
    if (tid < 128) {
        int a2 = blockIdx.x * 4 + (tid >> 5), j = tid & 31;
        g_tabi_s[a2 * 32 + j] = ts[a2 * 32 + j] * g_inv3[a2 * 4 + 0];
    } else if (tid < 192) {
        int t2 = tid - 128; int a2 = blockIdx.x * 4 + (t2 >> 4), j = t2 & 15;
        g_tabi_f[a2 * 16 + j] = tf[a2 * 16 + j] * g_inv3[a2 * 4 + 1];
    } else {
        int t2 = tid - 192; int a2 = blockIdx.x * 4 + (t2 >> 4), j = t2 & 15;
        g_tabi_sl[a2 * 16 + j] = tsl[a2 * 16 + j] * g_inv3[a2 * 4 + 2];
    }
}

// ============================================================================
// Stage 3: backward vector scan, 2 batches per warp, inv folded into tables.
// Lane groups: 0-7 sem/b0, 8-15 sem/b1, 16-19 fast/b0, 20-23 fast/b1,
//              24-27 slow/b0, 28-31 slow/b1. Each lane holds 4 floats.
// Serial chain per iter: d -> wd -> q -= wd*k'  (inv pre-folded).
// Scatter-at-produce gram pipelining, depth 4 (exact algebra).
// 64 blocks x 64 threads (4 batches/block).
// ============================================================================
// smem float offsets
#define SF_TAB_S   0
#define SF_TAB_F   2048
#define SF_TAB_SL  3072
#define SF_TABI_S  4096
#define SF_TABI_F  6144
#define SF_TABI_SL 7168
#define SF_G0      8192
#define SF_G1      12292    /* +4f stagger */
#define SF_G2      16392
#define SF_SC      20488
#define SF_SEQ     20744
#define SF_TOTF    (20744 + 8192)   /* seq: 4 batches x 2048 ints = 8192 slots */

__global__ void __launch_bounds__(64, 1) scan_kernel(
    const int* __restrict__ seq,
    const float* __restrict__ out_w, const float* __restrict__ out_b,
    float* __restrict__ out)
{
    extern __shared__ __align__(16) float smf[];
    int tid = threadIdx.x;

    // ---- fill shared ----
    {
        float4* d; const float4* s;
        d = (float4*)(smf + SF_TAB_S);   s = (const float4*)g_tab_s;
        for (int i = tid; i < 512; i += 64) d[i] = s[i];
        d = (float4*)(smf + SF_TAB_F);   s = (const float4*)g_tab_f;
        for (int i = tid; i < 256; i += 64) d[i] = s[i];
        d = (float4*)(smf + SF_TAB_SL);  s = (const float4*)g_tab_sl;
        for (int i = tid; i < 256; i += 64) d[i] = s[i];
        d = (float4*)(smf + SF_TABI_S);  s = (const float4*)g_tabi_s;
        for (int i = tid; i < 512; i += 64) d[i] = s[i];
        d = (float4*)(smf + SF_TABI_F);  s = (const float4*)g_tabi_f;
        for (int i = tid; i < 256; i += 64) d[i] = s[i];
        d = (float4*)(smf + SF_TABI_SL); s = (const float4*)g_tabi_sl;
        for (int i = tid; i < 256; i += 64) d[i] = s[i];
        d = (float4*)(smf + SF_G0); s = (const float4*)g_gram0;
        for (int i = tid; i < 1024; i += 64) d[i] = s[i];
        d = (float4*)(smf + SF_G1); s = (const float4*)g_gram1;
        for (int i = tid; i < 1024; i += 64) d[i] = s[i];
        d = (float4*)(smf + SF_G2); s = (const float4*)g_gram2;
        for (int i = tid; i < 1024; i += 64) d[i] = s[i];
        int4* di = (int4*)(smf + SF_SEQ);
        const int4* si = (const int4*)(seq + (size_t)blockIdx.x * 4 * LL);
        for (int i = tid; i < 2048; i += 64) di[i] = si[i];
    }
    __syncthreads();

    int warp = tid >> 5;
    int lane = tid & 31;
    int mem, bsel, e;
    if (lane < 16)      { mem = 0; bsel = (lane >> 3) & 1; e = lane & 7; }
    else if (lane < 24) { mem = 1; bsel = (lane >> 2) & 1; e = lane & 3; }
    else                { mem = 2; bsel = (lane >> 2) & 1; e = lane & 3; }
    int bloc = warp * 2 + bsel;
    int kstr = (mem == 0 ? 32 : 16);
    const float* tabb  = smf + (mem == 0 ? SF_TAB_S  : (mem == 1 ? SF_TAB_F  : SF_TAB_SL))  + e * 4;
    const float* tabbi = smf + (mem == 0 ? SF_TABI_S : (mem == 1 ? SF_TABI_F : SF_TABI_SL)) + e * 4;
    const float* gb    = smf + (mem == 0 ? SF_G0 : (mem == 1 ? SF_G1 : SF_G2));
    const int* sq = (const int*)(smf + SF_SEQ) + bloc * LL;
    float* scp = smf + SF_SC + bloc * 64;
    bool is_sem = (mem == 0);

    // ---- init: q = k_{L-1}, c = 0 ----
    int tl = sq[LL - 1];
    ulonglong2 qq = *(const ulonglong2*)(tabb + tl * kstr);
    u64 q0 = qq.x, q1 = qq.y;
    u64 c0 = pk(0.0f, 0.0f), c1 = pk(0.0f, 0.0f);

    // ---- pipeline rings, depth 4 ----
    float R_r[4];
    int tok_r[4];
    u64 k0_r[4], k1_r[4], ki0_r[4], ki1_r[4];

    #pragma unroll
    for (int j = 0; j < 4; j++) {
        int tau = sq[2046 - j];
        tok_r[j] = tau;
        ulonglong2 kk = *(const ulonglong2*)(tabb + tau * kstr);
        ulonglong2 kki = *(const ulonglong2*)(tabbi + tau * kstr);
        k0_r[j] = kk.x; k1_r[j] = kk.y;
        ki0_r[j] = kki.x; ki1_r[j] = kki.y;
        u64 pm = fmul2(kk.x, q0);
        pm = ffma2(kk.y, q1, pm);
        float2 pf = unpk(pm);
        float p = pf.x + pf.y;
        p += __shfl_xor_sync(0xffffffffu, p, 1);
        p += __shfl_xor_sync(0xffffffffu, p, 2);
        float p8 = p + __shfl_xor_sync(0xffffffffu, p, 4);
        R_r[j] = is_sem ? p8 : p;
    }

    const float invL = 1.0f / (float)LL;
    float uf = 2047.0f;

    #pragma unroll 4
    for (int it = 0; it < 2048; ++it) {
        int slot = it & 3;
        int ts = tok_r[slot];
        const float* grow = gb + ts * 64;
        float G1 = grow[tok_r[(slot + 1) & 3]];
        float G2 = grow[tok_r[(slot + 2) & 3]];
        float G3 = grow[tok_r[(slot + 3) & 3]];

        float d = R_r[slot];

        float wf = uf * invL;
        float wsl = sqrt_approx(wf);
        float wsem = (uf > 0.5f) ? 1.0f : 0.0f;
        float w = is_sem ? wsem : (mem == 1 ? wf : wsl);

        float wd = w * d;
        u64 wd2 = pk(wd, wd);
        u64 nwd2 = pk(-wd, -wd);
        c0 = ffma2(wd2, k0_r[slot], c0);
        c1 = ffma2(wd2, k1_r[slot], c1);
        q0 = ffma2(nwd2, ki0_r[slot], q0);   // inv pre-folded into ki
        q1 = ffma2(nwd2, ki1_r[slot], q1);

        float nwd = -wd;
        R_r[(slot + 1) & 3] = fmaf(nwd, G1, R_r[(slot + 1) & 3]);  // G' = G*inv_row
        R_r[(slot + 2) & 3] = fmaf(nwd, G2, R_r[(slot + 2) & 3]);
        R_r[(slot + 3) & 3] = fmaf(nwd, G3, R_r[(slot + 3) & 3]);

        // produce: dot for step s-4 against freshly updated q
        int sn = 2046 - it - 4;
        int idx = sn < 0 ? 0 : sn;
        int tau = sq[idx];
        tok_r[slot] = tau;
        ulonglong2 kk = *(const ulonglong2*)(tabb + tau * kstr);
        ulonglong2 kki = *(const ulonglong2*)(tabbi + tau * kstr);
        k0_r[slot] = kk.x; k1_r[slot] = kk.y;
        ki0_r[slot] = kki.x; ki1_r[slot] = kki.y;

        u64 pm = fmul2(kk.x, q0);
        pm = ffma2(kk.y, q1, pm);
        float2 pf = unpk(pm);
        float p = pf.x + pf.y;
        p += __shfl_xor_sync(0xffffffffu, p, 1);
        p += __shfl_xor_sync(0xffffffffu, p, 2);
        float p8 = p + __shfl_xor_sync(0xffffffffu, p, 4);
        R_r[slot] = is_sem ? p8 : p;

        uf -= 1.0f;
    }

    // ---- write c: [sem 0..31][fast 32..47][slow 48..63] ----
    {
        int off = (mem == 0 ? 0 : (mem == 1 ? 32 : 48)) + e * 4;
        *(u64*)(scp + off) = c0;
        *(u64*)(scp + off + 2) = c1;
    }
    __syncwarp();

    // ---- fused readout: 2 batches per warp, 2 cols per lane per batch ----
    {
        int batch0 = blockIdx.x * 4 + warp * 2;
        int v0 = 2 * lane;
        float2 bb = *(const float2*)(out_b + v0);
        #pragma unroll
        for (int bs = 0; bs < 2; bs++) {
            const float* cc = smf + SF_SC + (warp * 2 + bs) * 64;
            float acc0 = bb.x, acc1 = bb.y;
            #pragma unroll 8
            for (int dd = 0; dd < 64; dd++) {
                float cd = cc[dd];
                float2 wv = ((const float2*)out_w)[dd * 32 + lane];
                acc0 = fmaf(cd, wv.x, acc0);
                acc1 = fmaf(cd, wv.y, acc1);
            }
            *(float2*)(out + (batch0 + bs) * VOCAB + v0) = make_float2(acc0, acc1);
        }
    }
}

extern "C" void kernel_launch(void* const* d_in, const int* in_sizes, int n_in,
                              void* d_out, int out_size) {
    const int*   seq    = (const int*)  d_in[0];
    const float* embed  = (const float*)d_in[1];
    const float* w1     = (const float*)d_in[2];
    const float* b1     = (const float*)d_in[3];
    const float* w2     = (const float*)d_in[4];
    const float* b2     = (const float*)d_in[5];
    const float* ln_g   = (const float*)d_in[6];
    const float* ln_b   = (const float*)d_in[7];
    const float* sem_w  = (const float*)d_in[8];
    const float* sem_b  = (const float*)d_in[9];
    const float* fast_w = (const float*)d_in[10];
    const float* fast_b = (const float*)d_in[11];
    const float* slow_w = (const float*)d_in[12];
    const float* slow_b = (const float*)d_in[13];
    const float* out_w  = (const float*)d_in[14];
    const float* out_b  = (const float*)d_in[15];
    float* out = (float*)d_out;

    cudaFuncSetAttribute(tables_kernel,
                         cudaFuncAttributeMaxDynamicSharedMemorySize, TK_TOTF * 4);
    cudaFuncSetAttribute(scan_kernel,
                         cudaFuncAttributeMaxDynamicSharedMemorySize, SF_TOTF * 4);

    tables_kernel<<<16, 256, TK_TOTF * 4>>>(embed, w1, b1, w2, b2, ln_g, ln_b,
                                            sem_w, sem_b, fast_w, fast_b,
                                            slow_w, slow_b);
    gram_kernel<<<16, 256>>>();
    scan_kernel<<<64, 64, SF_TOTF * 4>>>(seq, out_w, out_b, out);
}

// round 17
// speedup vs baseline: 2.1365x; 1.0450x over previous
#include <cuda_runtime.h>

#define VOCAB 64
#define HID 64
#define SD 32
#define FD 16
#define SLD 16
#define BB 256
#define LL 2048

typedef unsigned long long u64;

// ---------- packed f32x2 helpers ----------
__device__ __forceinline__ u64 ffma2(u64 a, u64 b, u64 c) {
    u64 d;
    asm("fma.rn.f32x2 %0, %1, %2, %3;" : "=l"(d) : "l"(a), "l"(b), "l"(c));
    return d;
}
__device__ __forceinline__ u64 fmul2(u64 a, u64 b) {
    u64 d;
    asm("mul.rn.f32x2 %0, %1, %2;" : "=l"(d) : "l"(a), "l"(b));
    return d;
}
__device__ __forceinline__ float2 unpk(u64 u) {
    float2 f;
    asm("mov.b64 {%0,%1}, %2;" : "=f"(f.x), "=f"(f.y) : "l"(u));
    return f;
}
__device__ __forceinline__ u64 pk(float x, float y) {
    u64 u;
    asm("mov.b64 %0, {%1,%2};" : "=l"(u) : "f"(x), "f"(y));
    return u;
}
__device__ __forceinline__ float sqrt_approx(float x) {
    float r;
    asm("sqrt.approx.f32 %0, %1;" : "=f"(r) : "f"(x));
    return r;
}

// ---------- global scratch ----------
__device__ float g_tab_s[64 * SD];
__device__ float g_tab_f[64 * FD];
__device__ float g_tab_sl[64 * SLD];
__device__ float g_tabi_s[64 * SD];    // inv-scaled keys
__device__ float g_tabi_f[64 * FD];
__device__ float g_tabi_sl[64 * SLD];
__device__ float g_inv3[64 * 4];
__device__ float g_gram0[64 * 64];     // ROW-scaled: G'(a,b) = (k_a.k_b)*inv_a
__device__ float g_gram1[64 * 64];
__device__ float g_gram2[64 * 64];

// ============================================================================
// Stage 1 v3: one token per block, 64 blocks x 256 threads.
// Every matvec is split 4 ways over the contraction dim (quarters q=0..3,
// 16-long partials) and reduced through smem -> short chains, high occupancy.
// Weights are read from global (shared across blocks -> L2-resident).
// ============================================================================
__global__ void __launch_bounds__(256, 1) tables_kernel(
    const float* __restrict__ embed,
    const float* __restrict__ w1, const float* __restrict__ b1,
    const float* __restrict__ w2, const float* __restrict__ b2,
    const float* __restrict__ ln_g, const float* __restrict__ ln_b,
    const float* __restrict__ sem_w, const float* __restrict__ sem_b,
    const float* __restrict__ fast_w, const float* __restrict__ fast_b,
    const float* __restrict__ slow_w, const float* __restrict__ slow_b)
{
    __shared__ float se[64], h1[128], sx[64], shv[64], sk[64];
    __shared__ float p[512];   // partial sums, max 4 quarters x 128 outputs

    int tok = blockIdx.x;
    int tid = threadIdx.x;
    int q = tid >> 6;      // quarter 0..3
    int t = tid & 63;      // output/dim index

    if (tid < 64) se[t] = embed[tok * 64 + t];
    __syncthreads();

    // phase 1: h1 = relu(e @ w1 + b1): outputs m = t and t+64, partial over 16 j
    {
        float a0 = 0.0f, a1 = 0.0f;
        int j0 = q * 16;
        #pragma unroll
        for (int j = 0; j < 16; j++) {
            float ej = se[j0 + j];
            a0 = fmaf(ej, w1[(j0 + j) * 128 + t], a0);
            a1 = fmaf(ej, w1[(j0 + j) * 128 + 64 + t], a1);
        }
        p[q * 128 + t] = a0;
        p[q * 128 + 64 + t] = a1;
    }
    __syncthreads();
    if (tid < 128) {
        float v = b1[tid] + p[tid] + p[128 + tid] + p[256 + tid] + p[384 + tid];
        h1[tid] = fmaxf(v, 0.0f);
    }
    __syncthreads();

    // phase 2: x = e + h1 @ w2 + b2: output t, partial over 32 m
    {
        float a = 0.0f;
        int m0 = q * 32;
        #pragma unroll
        for (int m = 0; m < 32; m++)
            a = fmaf(h1[m0 + m], w2[(m0 + m) * 64 + t], a);
        p[q * 64 + t] = a;
    }
    __syncthreads();
    if (tid < 64) {
        sx[t] = se[t] + b2[t] + p[t] + p[64 + t] + p[128 + t] + p[192 + t];
    }
    __syncthreads();

    // layernorm (64 threads, redundant reductions -- short)
    if (tid < 64) {
        float mu = 0.0f;
        #pragma unroll 8
        for (int j = 0; j < 64; j++) mu += sx[j];
        mu *= (1.0f / HID);
        float var = 0.0f;
        #pragma unroll 8
        for (int j = 0; j < 64; j++) { float dd = sx[j] - mu; var = fmaf(dd, dd, var); }
        var *= (1.0f / HID);
        shv[t] = (sx[t] - mu) * rsqrtf(var + 1e-5f) * ln_g[t] + ln_b[t];
    }
    __syncthreads();

    // projections: packed output dim t (0-31 sem, 32-47 fast, 48-63 slow),
    // partial over 16 j per quarter
    {
        float a = 0.0f;
        int j0 = q * 16;
        if (t < 32) {
            #pragma unroll
            for (int j = 0; j < 16; j++) a = fmaf(shv[j0 + j], sem_w[(j0 + j) * SD + t], a);
        } else if (t < 48) {
            int d = t - 32;
            #pragma unroll
            for (int j = 0; j < 16; j++) a = fmaf(shv[j0 + j], fast_w[(j0 + j) * FD + d], a);
        } else {
            int d = t - 48;
            #pragma unroll
            for (int j = 0; j < 16; j++) a = fmaf(shv[j0 + j], slow_w[(j0 + j) * SLD + d], a);
        }
        p[q * 64 + t] = a;
    }
    __syncthreads();
    if (tid < 64) {
        float bias = t < 32 ? sem_b[t] : (t < 48 ? fast_b[t - 32] : slow_b[t - 48]);
        float v = bias + p[t] + p[64 + t] + p[128 + t] + p[192 + t];
        if (t < 32) g_tab_s[tok * SD + t] = v;
        else if (t < 48) g_tab_f[tok * FD + (t - 32)] = v;
        else g_tab_sl[tok * SLD + (t - 48)] = v;
        sk[t] = v;
    }
    __syncthreads();

    if (tid == 0) {
        float s = 0.0f;
        #pragma unroll
        for (int j = 0; j < 32; j++) s = fmaf(sk[j], sk[j], s);
        g_inv3[tok * 4 + 0] = 1.0f / (s + 1e-6f);
    } else if (tid == 1) {
        float s = 0.0f;
        #pragma unroll
        for (int j = 32; j < 48; j++) s = fmaf(sk[j], sk[j], s);
        g_inv3[tok * 4 + 1] = 1.0f / (s + 1e-6f);
    } else if (tid == 2) {
        float s = 0.0f;
        #pragma unroll
        for (int j = 48; j < 64; j++) s = fmaf(sk[j], sk[j], s);
        g_inv3[tok * 4 + 2] = 1.0f / (s + 1e-6f);
    }
}

// ============================================================================
// Stage 2 v2: one Gram ROW per block (64 blocks x 256 threads, 192 active).
// Row a staged to smem; columns read from L2. ROW-scaled G'(a,b)=G(a,b)*inv_a
// (the scan's scatter needs inv of the CONSUMED token = the row index).
// Also emits the inv-scaled key tables.
// ============================================================================
__global__ void __launch_bounds__(256, 1) gram_kernel()
{
    __shared__ float row[64];   // [0:32) sem | [32:48) fast | [48:64) slow
    __shared__ float inv_a[4];
    int a = blockIdx.x;
    int tid = threadIdx.x;

    if (tid < 32) row[tid] = g_tab_s[a * SD + tid];
    else if (tid < 48) row[tid] = g_tab_f[a * FD + (tid - 32)];
    else if (tid < 64) row[tid] = g_tab_sl[a * SLD + (tid - 48)];
    if (tid >= 64 && tid < 67) inv_a[tid - 64] = g_inv3[a * 4 + (tid - 64)];
    __syncthreads();

    if (tid < 64) {
        int b = tid;
        float ds = 0.0f;
        #pragma unroll
        for (int j = 0; j < 32; j++) ds = fmaf(row[j], g_tab_s[b * SD + j], ds);
        g_gram0[a * 64 + b] = ds * inv_a[0];
        // inv-scaled key tables for token a (reuse these threads)
        if (b < 32) g_tabi_s[a * SD + b] = row[b] * inv_a[0];
        else if (b < 48) g_tabi_f[a * FD + (b - 32)] = row[b] * inv_a[1];
        else g_tabi_sl[a * SLD + (b - 48)] = row[b] * inv_a[2];
    } else if (tid < 128) {
        int b = tid - 64;
        float df = 0.0f;
        #pragma unroll
        for (int j = 0; j < 16; j++) df = fmaf(row[32 + j], g_tab_f[b * FD + j], df);
        g_gram1[a * 64 + b] = df * inv_a[1];
    } else if (tid < 192) {
        int b = tid - 128;
        float dsl = 0.0f;
        #pragma unroll
        for (int j = 0; j < 16; j++) dsl = fmaf(row[48 + j], g_tab_sl[b * SLD + j], dsl);
        g_gram2[a * 64 + b] = dsl * inv_a[2];
    }
}

// ============================================================================
// Stage 3: backward vector scan, 2 batches per warp, inv folded into tables.
// (unchanged from the passing R16 kernel)
// ============================================================================
// smem float offsets
#define SF_TAB_S   0
#define SF_TAB_F   2048
#define SF_TAB_SL  3072
#define SF_TABI_S  4096
#define SF_TABI_F  6144
#define SF_TABI_SL 7168
#define SF_G0      8192
#define SF_G1      12292    /* +4f stagger */
#define SF_G2      16392
#define SF_SC      20488
#define SF_SEQ     20744
#define SF_TOTF    (20744 + 8192)   /* seq: 4 batches x 2048 ints */

__global__ void __launch_bounds__(64, 1) scan_kernel(
    const int* __restrict__ seq,
    const float* __restrict__ out_w, const float* __restrict__ out_b,
    float* __restrict__ out)
{
    extern __shared__ __align__(16) float smf[];
    int tid = threadIdx.x;

    // ---- fill shared ----
    {
        float4* d; const float4* s;
        d = (float4*)(smf + SF_TAB_S);   s = (const float4*)g_tab_s;
        for (int i = tid; i < 512; i += 64) d[i] = s[i];
        d = (float4*)(smf + SF_TAB_F);   s = (const float4*)g_tab_f;
        for (int i = tid; i < 256; i += 64) d[i] = s[i];
        d = (float4*)(smf + SF_TAB_SL);  s = (const float4*)g_tab_sl;
        for (int i = tid; i < 256; i += 64) d[i] = s[i];
        d = (float4*)(smf + SF_TABI_S);  s = (const float4*)g_tabi_s;
        for (int i = tid; i < 512; i += 64) d[i] = s[i];
        d = (float4*)(smf + SF_TABI_F);  s = (const float4*)g_tabi_f;
        for (int i = tid; i < 256; i += 64) d[i] = s[i];
        d = (float4*)(smf + SF_TABI_SL); s = (const float4*)g_tabi_sl;
        for (int i = tid; i < 256; i += 64) d[i] = s[i];
        d = (float4*)(smf + SF_G0); s = (const float4*)g_gram0;
        for (int i = tid; i < 1024; i += 64) d[i] = s[i];
        d = (float4*)(smf + SF_G1); s = (const float4*)g_gram1;
        for (int i = tid; i < 1024; i += 64) d[i] = s[i];
        d = (float4*)(smf + SF_G2); s = (const float4*)g_gram2;
        for (int i = tid; i < 1024; i += 64) d[i] = s[i];
        int4* di = (int4*)(smf + SF_SEQ);
        const int4* si = (const int4*)(seq + (size_t)blockIdx.x * 4 * LL);
        for (int i = tid; i < 2048; i += 64) di[i] = si[i];
    }
    __syncthreads();

    int warp = tid >> 5;
    int lane = tid & 31;
    int mem, bsel, e;
    if (lane < 16)      { mem = 0; bsel = (lane >> 3) & 1; e = lane & 7; }
    else if (lane < 24) { mem = 1; bsel = (lane >> 2) & 1; e = lane & 3; }
    else                { mem = 2; bsel = (lane >> 2) & 1; e = lane & 3; }
    int bloc = warp * 2 + bsel;
    int kstr = (mem == 0 ? 32 : 16);
    const float* tabb  = smf + (mem == 0 ? SF_TAB_S  : (mem == 1 ? SF_TAB_F  : SF_TAB_SL))  + e * 4;
    const float* tabbi = smf + (mem == 0 ? SF_TABI_S : (mem == 1 ? SF_TABI_F : SF_TABI_SL)) + e * 4;
    const float* gb    = smf + (mem == 0 ? SF_G0 : (mem == 1 ? SF_G1 : SF_G2));
    const int* sq = (const int*)(smf + SF_SEQ) + bloc * LL;
    float* scp = smf + SF_SC + bloc * 64;
    bool is_sem = (mem == 0);

    // ---- init: q = k_{L-1}, c = 0 ----
    int tl = sq[LL - 1];
    ulonglong2 qq = *(const ulonglong2*)(tabb + tl * kstr);
    u64 q0 = qq.x, q1 = qq.y;
    u64 c0 = pk(0.0f, 0.0f), c1 = pk(0.0f, 0.0f);

    // ---- pipeline rings, depth 4 ----
    float R_r[4];
    int tok_r[4];
    u64 k0_r[4], k1_r[4], ki0_r[4], ki1_r[4];

    #pragma unroll
    for (int j = 0; j < 4; j++) {
        int tau = sq[2046 - j];
        tok_r[j] = tau;
        ulonglong2 kk = *(const ulonglong2*)(tabb + tau * kstr);
        ulonglong2 kki = *(const ulonglong2*)(tabbi + tau * kstr);
        k0_r[j] = kk.x; k1_r[j] = kk.y;
        ki0_r[j] = kki.x; ki1_r[j] = kki.y;
        u64 pm = fmul2(kk.x, q0);
        pm = ffma2(kk.y, q1, pm);
        float2 pf = unpk(pm);
        float p = pf.x + pf.y;
        p += __shfl_xor_sync(0xffffffffu, p, 1);
        p += __shfl_xor_sync(0xffffffffu, p, 2);
        float p8 = p + __shfl_xor_sync(0xffffffffu, p, 4);
        R_r[j] = is_sem ? p8 : p;
    }

    const float invL = 1.0f / (float)LL;
    float uf = 2047.0f;

    #pragma unroll 4
    for (int it = 0; it < 2048; ++it) {
        int slot = it & 3;
        int ts = tok_r[slot];
        const float* grow = gb + ts * 64;
        float G1 = grow[tok_r[(slot + 1) & 3]];
        float G2 = grow[tok_r[(slot + 2) & 3]];
        float G3 = grow[tok_r[(slot + 3) & 3]];

        float d = R_r[slot];

        float wf = uf * invL;
        float wsl = sqrt_approx(wf);
        float wsem = (uf > 0.5f) ? 1.0f : 0.0f;
        float w = is_sem ? wsem : (mem == 1 ? wf : wsl);

        float wd = w * d;
        u64 wd2 = pk(wd, wd);
        u64 nwd2 = pk(-wd, -wd);
        c0 = ffma2(wd2, k0_r[slot], c0);
        c1 = ffma2(wd2, k1_r[slot], c1);
        q0 = ffma2(nwd2, ki0_r[slot], q0);   // inv pre-folded into ki
        q1 = ffma2(nwd2, ki1_r[slot], q1);

        float nwd = -wd;
        R_r[(slot + 1) & 3] = fmaf(nwd, G1, R_r[(slot + 1) & 3]);  // G' = G*inv_row
        R_r[(slot + 2) & 3] = fmaf(nwd, G2, R_r[(slot + 2) & 3]);
        R_r[(slot + 3) & 3] = fmaf(nwd, G3, R_r[(slot + 3) & 3]);

        // produce: dot for step s-4 against freshly updated q
        int sn = 2046 - it - 4;
        int idx = sn < 0 ? 0 : sn;
        int tau = sq[idx];
        tok_r[slot] = tau;
        ulonglong2 kk = *(const ulonglong2*)(tabb + tau * kstr);
        ulonglong2 kki = *(const ulonglong2*)(tabbi + tau * kstr);
        k0_r[slot] = kk.x; k1_r[slot] = kk.y;
        ki0_r[slot] = kki.x; ki1_r[slot] = kki.y;

        u64 pm = fmul2(kk.x, q0);
        pm = ffma2(kk.y, q1, pm);
        float2 pf = unpk(pm);
        float p = pf.x + pf.y;
        p += __shfl_xor_sync(0xffffffffu, p, 1);
        p += __shfl_xor_sync(0xffffffffu, p, 2);
        float p8 = p + __shfl_xor_sync(0xffffffffu, p, 4);
        R_r[slot] = is_sem ? p8 : p;

        uf -= 1.0f;
    }

    // ---- write c: [sem 0..31][fast 32..47][slow 48..63] ----
    {
        int off = (mem == 0 ? 0 : (mem == 1 ? 32 : 48)) + e * 4;
        *(u64*)(scp + off) = c0;
        *(u64*)(scp + off + 2) = c1;
    }
    __syncwarp();

    // ---- fused readout: 2 batches per warp, 2 cols per lane per batch ----
    {
        int batch0 = blockIdx.x * 4 + warp * 2;
        int v0 = 2 * lane;
        float2 bb = *(const float2*)(out_b + v0);
        #pragma unroll
        for (int bs = 0; bs < 2; bs++) {
            const float* cc = smf + SF_SC + (warp * 2 + bs) * 64;
            float acc0 = bb.x, acc1 = bb.y;
            #pragma unroll 8
            for (int dd = 0; dd < 64; dd++) {
                float cd = cc[dd];
                float2 wv = ((const float2*)out_w)[dd * 32 + lane];
                acc0 = fmaf(cd, wv.x, acc0);
                acc1 = fmaf(cd, wv.y, acc1);
            }
            *(float2*)(out + (batch0 + bs) * VOCAB + v0) = make_float2(acc0, acc1);
        }
    }
}

extern "C" void kernel_launch(void* const* d_in, const int* in_sizes, int n_in,
                              void* d_out, int out_size) {
    const int*   seq    = (const int*)  d_in[0];
    const float* embed  = (const float*)d_in[1];
    const float* w1     = (const float*)d_in[2];
    const float* b1     = (const float*)d_in[3];
    const float* w2     = (const float*)d_in[4];
    const float* b2     = (const float*)d_in[5];
    const float* ln_g   = (const float*)d_in[6];
    const float* ln_b   = (const float*)d_in[7];
    const float* sem_w  = (const float*)d_in[8];
    const float* sem_b  = (const float*)d_in[9];
    const float* fast_w = (const float*)d_in[10];
    const float* fast_b = (const float*)d_in[11];
    const float* slow_w = (const float*)d_in[12];
    const float* slow_b = (const float*)d_in[13];
    const float* out_w  = (const float*)d_in[14];
    const float* out_b  = (const float*)d_in[15];
    float* out = (float*)d_out;

    cudaFuncSetAttribute(scan_kernel,
                         cudaFuncAttributeMaxDynamicSharedMemorySize, SF_TOTF * 4);

    tables_kernel<<<64, 256>>>(embed, w1, b1, w2, b2, ln_g, ln_b,
                               sem_w, sem_b, fast_w, fast_b,
                               slow_w, slow_b);
    gram_kernel<<<64, 256>>>();
    scan_kernel<<<64, 64, SF_TOTF * 4>>>(seq, out_w, out_b, out);
}